// round 3
// baseline (speedup 1.0000x reference)
#include <cuda_runtime.h>
#include <cstdint>
#include <cstddef>

#define HH 512
#define WW 512
#define NIMG 16
#define NPIX (HH*WW)
#define OD 2045

// ---------------- device scratch (static; no allocations) ----------------
__device__ unsigned char g_b12a[(size_t)NIMG*NPIX*12];         // ping (NHWC c12, byte-packed)
__device__ unsigned char g_b12b[(size_t)NIMG*NPIX*12];         // pong
__device__ int   g_w0p[400];   // [tap25][oc16] (w-128)
__device__ int   g_w1p[48];    // [oc12][4 words of ic16]
__device__ int   g_w35p[4][324];  // layers 2..5: [(oc*9+tap)*3 + word]
__device__ int   g_w6p[48];    // [oc16][3 words of ic12]
// deconv weights, channel-paired, valid taps only:
// [j=cpair(8)][seq(81), padded to 82] -> float2 (c=2j, c=2j+1)
__device__ __align__(16) float2 g_pw2[8*82];

// ---------------- weight packing ----------------
__global__ void pack_weights_kernel(const int* __restrict__ w0, const int* __restrict__ w1,
                                    const int* __restrict__ w2, const int* __restrict__ w3,
                                    const int* __restrict__ w4, const int* __restrict__ w5,
                                    const int* __restrict__ w6, const float* __restrict__ wt)
{
    int tid = threadIdx.x;
    for (int idx = tid; idx < 400; idx += blockDim.x) {
        int t = idx / 16, o = idx % 16;
        g_w0p[idx] = w0[o*25 + t] - 128;
    }
    for (int idx = tid; idx < 48; idx += blockDim.x) {
        int o = idx / 4, j = idx % 4;
        unsigned r = 0;
        for (int b = 0; b < 4; b++) {
            int v = w1[o*16 + j*4 + b] - 128;
            r |= ((unsigned)(v & 255)) << (8*b);
        }
        g_w1p[idx] = (int)r;
    }
    for (int l = 0; l < 4; l++) {
        const int* ws = (l == 0) ? w2 : (l == 1) ? w3 : (l == 2) ? w4 : w5;
        for (int idx = tid; idx < 324; idx += blockDim.x) {
            int o = idx / 27;
            int rem = idx % 27;
            int t = rem / 3, j = rem % 3;
            unsigned r = 0;
            for (int b = 0; b < 4; b++) {
                int i = j*4 + b;
                int v = ws[(o*12 + i)*9 + t] - 128;
                r |= ((unsigned)(v & 255)) << (8*b);
            }
            g_w35p[l][idx] = (int)r;
        }
    }
    for (int idx = tid; idx < 48; idx += blockDim.x) {
        int o = idx / 3, j = idx % 3;
        unsigned r = 0;
        for (int b = 0; b < 4; b++) {
            int v = w6[o*12 + j*4 + b] - 128;
            r |= ((unsigned)(v & 255)) << (8*b);
        }
        g_w6p[idx] = (int)r;
    }
    // deconv phase weights (valid taps only; order must match deconv_kernel):
    // out(ry,rx) at grid G uses input (G+dy,G+dx) with a = 4*dy + 4 - ry,
    // b = 4*dx + 4 - rx; valid iff a,b in [0,8]; k[0][c][a][b] = wt[c][0][8-a][8-b].
    if (tid < 8) {
        int j = tid;
        int seq = 0;
        for (int ry = 0; ry < 4; ry++)
        for (int rx = 0; rx < 4; rx++)
        for (int dy = -1; dy <= 1; dy++) {
            if (dy < 0 && ry != 0) continue;
            for (int dx = -1; dx <= 1; dx++) {
                if (dx < 0 && rx != 0) continue;
                int a = 4*dy + 4 - ry;
                int b = 4*dx + 4 - rx;
                float v0 = wt[(2*j + 0)*81 + (8 - a)*9 + (8 - b)];
                float v1 = wt[(2*j + 1)*81 + (8 - a)*9 + (8 - b)];
                g_pw2[j*82 + seq] = make_float2(v0, v1);
                seq++;
            }
        }
    }
}

__device__ __forceinline__ int requant(int acc, float M)
{
    float q = rintf((float)acc * M);     // half-to-even, matches jnp.round
    q = fminf(fmaxf(q, 0.f), 127.f);     // clamp[-127,127] ∘ relu == clamp[0,127]
    return (int)q;
}

// ---------------- fused quant + conv0(k5,1->16) + conv1(1x1,16->12) ----------------
__global__ __launch_bounds__(256) void conv01_kernel(const float* __restrict__ x,
                                                     const int* __restrict__ b0,
                                                     const int* __restrict__ b1,
                                                     float M0, float M1)
{
    __shared__ unsigned char tile[12][36];
    __shared__ int w0sm[400];
    __shared__ int w1sm[48];
    __shared__ int b0sm[16];
    __shared__ int b1sm[12];
    int tid = threadIdx.y*32 + threadIdx.x;
    for (int i = tid; i < 400; i += 256) w0sm[i] = g_w0p[i];
    if (tid < 48) w1sm[tid] = g_w1p[tid];
    if (tid < 16) b0sm[tid] = b0[tid];
    if (tid >= 32 && tid < 44) b1sm[tid - 32] = b1[tid - 32];

    int n = blockIdx.z;
    int x0 = blockIdx.x*32, y0 = blockIdx.y*8;
    const float* in = x + (size_t)n*NPIX;
    const float in_s = (float)(1.0/255.0);
    for (int i = tid; i < 12*36; i += 256) {
        int iy = i / 36, ix = i % 36;
        int gy = y0 + iy - 2, gx = x0 + ix - 2;
        unsigned char v = 0;
        if (gy >= 0 && gy < HH && gx >= 0 && gx < WW) {
            float q = rintf(__fdiv_rn(in[gy*WW + gx], in_s));
            q = fminf(fmaxf(q, 0.f), 255.f);
            v = (unsigned char)(int)q;
        }
        tile[iy][ix] = v;
    }
    __syncthreads();

    int acc[16];
#pragma unroll
    for (int c = 0; c < 16; c++) acc[c] = b0sm[c];
#pragma unroll
    for (int t = 0; t < 25; t++) {
        int dy = t / 5, dx = t % 5;
        int v = tile[threadIdx.y + dy][threadIdx.x + dx];
#pragma unroll
        for (int c = 0; c < 16; c++) acc[c] += v * w0sm[t*16 + c];
    }
    int aw[4];
#pragma unroll
    for (int j = 0; j < 4; j++) {
        unsigned w = 0;
#pragma unroll
        for (int b = 0; b < 4; b++)
            w |= ((unsigned)requant(acc[j*4 + b], M0)) << (8*b);
        aw[j] = (int)w;
    }
    int out3[3];
#pragma unroll
    for (int og = 0; og < 3; og++) {
        unsigned word = 0;
#pragma unroll
        for (int ob = 0; ob < 4; ob++) {
            int o = og*4 + ob;
            int a = b1sm[o];
            a = __dp4a(aw[0], w1sm[o*4 + 0], a);
            a = __dp4a(aw[1], w1sm[o*4 + 1], a);
            a = __dp4a(aw[2], w1sm[o*4 + 2], a);
            a = __dp4a(aw[3], w1sm[o*4 + 3], a);
            word |= ((unsigned)requant(a, M1)) << (8*ob);
        }
        out3[og] = (int)word;
    }
    int* outp = (int*)g_b12a + ((size_t)n*NPIX + (size_t)(y0 + threadIdx.y)*WW + x0 + threadIdx.x)*3;
    outp[0] = out3[0];
    outp[1] = out3[1];
    outp[2] = out3[2];
}

// ---------------- conv3x3: 12 -> 12, pad1 (layers 2..5) ----------------
// layer selects the weight table; parity selects ping/pong direction.
__global__ __launch_bounds__(256) void conv3_kernel(int layer,
                                                    const int* __restrict__ bias, float M)
{
    __shared__ int tile[10][34*3];
    __shared__ int wsm[324];
    __shared__ int bsm[12];
    int tid = threadIdx.y*32 + threadIdx.x;
    for (int i = tid; i < 324; i += 256) wsm[i] = g_w35p[layer][i];
    if (tid < 12) bsm[tid] = bias[tid];
    int flip = layer & 1;
    int n = blockIdx.z;
    int x0 = blockIdx.x*32, y0 = blockIdx.y*8;
    const int* in  = (const int*)(flip ? g_b12b : g_b12a) + (size_t)n*NPIX*3;
    int*      outb = (int*)(flip ? g_b12a : g_b12b);
    for (int i = tid; i < 340; i += 256) {
        int iy = i / 34, ix = i % 34;
        int gy = y0 + iy - 1, gx = x0 + ix - 1;
        if (gy >= 0 && gy < HH && gx >= 0 && gx < WW) {
            size_t base = (size_t)(gy*WW + gx)*3;
            tile[iy][ix*3 + 0] = in[base + 0];
            tile[iy][ix*3 + 1] = in[base + 1];
            tile[iy][ix*3 + 2] = in[base + 2];
        } else {
            tile[iy][ix*3 + 0] = 0;
            tile[iy][ix*3 + 1] = 0;
            tile[iy][ix*3 + 2] = 0;
        }
    }
    __syncthreads();

    int v[27];
#pragma unroll
    for (int t = 0; t < 9; t++) {
        int dy = t / 3, dx = t % 3;
#pragma unroll
        for (int j = 0; j < 3; j++)
            v[t*3 + j] = tile[threadIdx.y + dy][(threadIdx.x + dx)*3 + j];
    }
    int out3[3];
#pragma unroll
    for (int og = 0; og < 3; og++) {
        unsigned word = 0;
#pragma unroll
        for (int ob = 0; ob < 4; ob++) {
            int o = og*4 + ob;
            int acc = bsm[o];
#pragma unroll
            for (int t = 0; t < 9; t++) {
                acc = __dp4a(v[t*3 + 0], wsm[(o*9 + t)*3 + 0], acc);
                acc = __dp4a(v[t*3 + 1], wsm[(o*9 + t)*3 + 1], acc);
                acc = __dp4a(v[t*3 + 2], wsm[(o*9 + t)*3 + 2], acc);
            }
            word |= ((unsigned)requant(acc, M)) << (8*ob);
        }
        out3[og] = (int)word;
    }
    int* outp = outb + ((size_t)n*NPIX + (size_t)(y0 + threadIdx.y)*WW + x0 + threadIdx.x)*3;
    outp[0] = out3[0];
    outp[1] = out3[1];
    outp[2] = out3[2];
}

// ---------------- fused conv6(1x1,12->16) + deconv(16->1,k9,s4,p4) ----------------
__global__ __launch_bounds__(256) void deconv_kernel(const int* __restrict__ b6,
                                                     float M6, float out_s,
                                                     float* __restrict__ out)
{
    __shared__ float2 sin2[8][18][18];   // channel-pair j -> (c=2j, c=2j+1)
    __shared__ ulonglong2 wsm[8*41];     // g_pw2 as 16B vectors (82 float2 per j = 41)
    __shared__ int w6sm[48];
    __shared__ int b6sm[16];
    __shared__ float stile[64*64];       // output staging for coalesced store
    int tid = threadIdx.y*16 + threadIdx.x;
    for (int i = tid; i < 328; i += 256) wsm[i] = ((const ulonglong2*)g_pw2)[i];
    if (tid < 48) w6sm[tid] = g_w6p[tid];
    if (tid >= 64 && tid < 80) b6sm[tid - 64] = b6[tid - 64];
    __syncthreads();   // w6sm/b6sm needed by the tile loader below

    int n = blockIdx.z;
    int gy0 = blockIdx.y*16, gx0 = blockIdx.x*16;
    const int* in = (const int*)g_b12a + (size_t)n*NPIX*3;
    for (int u = tid; u < 324; u += 256) {
        int iy = u / 18, ix = u % 18;
        int gy = gy0 + iy - 1, gx = gx0 + ix - 1;
        if (gy >= 0 && gy < HH && gx >= 0 && gx < WW) {
            size_t base = (size_t)(gy*WW + gx)*3;
            int v0 = in[base + 0], v1 = in[base + 1], v2 = in[base + 2];
            float r[16];
#pragma unroll
            for (int o = 0; o < 16; o++) {
                int a = b6sm[o];
                a = __dp4a(v0, w6sm[o*3 + 0], a);
                a = __dp4a(v1, w6sm[o*3 + 1], a);
                a = __dp4a(v2, w6sm[o*3 + 2], a);
                r[o] = (float)requant(a, M6) * out_s;
            }
#pragma unroll
            for (int j = 0; j < 8; j++)
                sin2[j][iy][ix] = make_float2(r[2*j], r[2*j + 1]);
        } else {
#pragma unroll
            for (int j = 0; j < 8; j++)
                sin2[j][iy][ix] = make_float2(0.f, 0.f);
        }
    }
    __syncthreads();

    unsigned long long acc2[16];
#pragma unroll
    for (int i = 0; i < 16; i++) acc2[i] = 0ULL;

    for (int j = 0; j < 8; j++) {
        unsigned long long v2[9];
#pragma unroll
        for (int t = 0; t < 9; t++)
            v2[t] = *reinterpret_cast<const unsigned long long*>(
                        &sin2[j][threadIdx.y + t/3][threadIdx.x + t%3]);
        const ulonglong2* wj = &wsm[j*41];
        int seq = 0;
        ulonglong2 wpair;
#pragma unroll
        for (int ry = 0; ry < 4; ry++)
#pragma unroll
        for (int rx = 0; rx < 4; rx++) {
            const int p = ry*4 + rx;
#pragma unroll
            for (int dy = -1; dy <= 1; dy++) {
                if (dy < 0 && ry != 0) continue;
#pragma unroll
                for (int dx = -1; dx <= 1; dx++) {
                    if (dx < 0 && rx != 0) continue;
                    if ((seq & 1) == 0) wpair = wj[seq >> 1];
                    unsigned long long w = (seq & 1) ? wpair.y : wpair.x;
                    asm("fma.rn.f32x2 %0, %1, %2, %0;"
                        : "+l"(acc2[p])
                        : "l"(v2[(dy + 1)*3 + (dx + 1)]), "l"(w));
                    seq++;
                }
            }
        }
    }
    // horizontal add of channel halves + stage to smem
#pragma unroll
    for (int p = 0; p < 16; p++) {
        float lo, hi;
        asm("mov.b64 {%0, %1}, %2;" : "=f"(lo), "=f"(hi) : "l"(acc2[p]));
        stile[(threadIdx.y*4 + (p >> 2))*64 + threadIdx.x*4 + (p & 3)] = lo + hi;
    }
    __syncthreads();

    float* outn = out + (size_t)n*OD*OD;
    int oy_base = blockIdx.y*64, ox_base = blockIdx.x*64;
    for (int u = tid; u < 4096; u += 256) {
        int oyl = u >> 6, oxl = u & 63;
        int oy = oy_base + oyl, ox = ox_base + oxl;
        if (oy < OD && ox < OD)
            outn[(size_t)oy*OD + ox] = stile[u];
    }
}

// ---------------- launch ----------------
extern "C" void kernel_launch(void* const* d_in, const int* in_sizes, int n_in,
                              void* d_out, int out_size)
{
    const float* x = (const float*)d_in[0];
    const int* w[7];
    const int* b[7];
    const float* wt;
    if (in_sizes[2] == 16) {
        // interleaved: x, w0, b0, w1, b1, ..., w6, b6, wt
        for (int i = 0; i < 7; i++) {
            w[i] = (const int*)d_in[1 + 2*i];
            b[i] = (const int*)d_in[2 + 2*i];
        }
    } else {
        // grouped: x, w0..w6, b0..b6, wt
        for (int i = 0; i < 7; i++) {
            w[i] = (const int*)d_in[1 + i];
            b[i] = (const int*)d_in[8 + i];
        }
    }
    wt = (const float*)d_in[15];

    // requant multipliers: python-double products cast to f32 (matches reference scalars)
    float M0 = (float)((1.0/255.0) * 0.02 / 0.05);
    float M1 = (float)(0.05 * 0.02 / 0.04);
    float M2 = (float)(0.04 * 0.02 / 0.04);
    float M6 = (float)(0.04 * 0.02 / 0.05);

    pack_weights_kernel<<<1, 256>>>(w[0], w[1], w[2], w[3], w[4], w[5], w[6], wt);

    dim3 cblk(32, 8);
    dim3 cgrd(WW/32, HH/8, NIMG);
    conv01_kernel<<<cgrd, cblk>>>(x, b[0], b[1], M0, M1);

    conv3_kernel<<<cgrd, cblk>>>(0, b[2], M2);   // A -> B
    conv3_kernel<<<cgrd, cblk>>>(1, b[3], M2);   // B -> A
    conv3_kernel<<<cgrd, cblk>>>(2, b[4], M2);   // A -> B
    conv3_kernel<<<cgrd, cblk>>>(3, b[5], M2);   // B -> A

    dim3 dblk(16, 16);
    dim3 dgrd(32, 32, NIMG);
    deconv_kernel<<<dgrd, dblk>>>(b[6], M6, 0.05f, (float*)d_out);

    (void)n_in; (void)out_size;
}